// round 4
// baseline (speedup 1.0000x reference)
#include <cuda_runtime.h>
#include <cuda_bf16.h>
#include <cstdint>

// Problem constants
#define B_    8
#define N_    1024
#define FIN   256
#define NH    8
#define ND    32
#define M_TOT (B_ * N_)      // 8192
#define NBH   (B_ * NH)      // 64
#define ROWS  1025
#define OCOLS (NH * ND)      // 256

// ---------------- scratch ----------------
__device__ float g_buf[M_TOT * OCOLS];        // g[m][h*32+d] fp32
__device__ float ssrc_buf[NBH * N_];          // [bh][n]
__device__ float sdst_buf[NBH * N_];          // [bh][n]
__device__ float vsort_buf[NBH * N_];
__device__ int   sid_buf[NBH * N_];
__device__ float suf1_buf[NBH * ROWS * ND];
__device__ float pre2_buf[NBH * ROWS * ND];
__device__ float c1_buf[NBH * ROWS];
__device__ float c2_buf[NBH * ROWS];
__device__ float cb1_buf[NBH * 32 * 32];      // [bh][chunk][d]: inclusive-suffix base
__device__ float cb2_buf[NBH * 32 * 32];      // [bh][chunk][d]: exclusive-prefix base
__device__ float4 qscal_buf[NBH * N_];        // [bh][n]: {E1/den, E2/den, bits(t), 0}

// ---------------- mma.sync helper ----------------
#define MMA_BF16(d, a, b)                                                      \
    asm volatile("mma.sync.aligned.m16n8k16.row.col.f32.bf16.bf16.f32 "        \
        "{%0,%1,%2,%3}, {%4,%5,%6,%7}, {%8,%9}, {%0,%1,%2,%3};"                \
        : "+f"((d)[0]), "+f"((d)[1]), "+f"((d)[2]), "+f"((d)[3])               \
        : "r"((a)[0]), "r"((a)[1]), "r"((a)[2]), "r"((a)[3]),                  \
          "r"((b)[0]), "r"((b)[1]))

// ---------------- kernel 1: g = vertex @ w_vert via HMMA bf16 hi/lo ----------------
// Tile 64m x 128n, grid (2, 128) = 256 CTAs, 8 warps (2m x 4n), warp tile 32x32.
#define KC 32
#define APAD 8
__global__ __launch_bounds__(256) void gemm_mma_k(const float* __restrict__ A,
                                                  const float* __restrict__ W) {
    __shared__ __align__(16) __nv_bfloat16 Ah[64][KC + APAD];
    __shared__ __align__(16) __nv_bfloat16 Al[64][KC + APAD];
    __shared__ __align__(16) __nv_bfloat16 Bh[128][KC + APAD];
    __shared__ __align__(16) __nv_bfloat16 Bl[128][KC + APAD];

    const int tid = threadIdx.x;
    const int wid = tid >> 5, lane = tid & 31;
    const int wm = wid >> 2, wn = wid & 3;
    const int rowBase = blockIdx.y * 64;
    const int colBase = blockIdx.x * 128;
    const int g = lane >> 2, tg = lane & 3;

    float acc[2][4][4];
#pragma unroll
    for (int mt = 0; mt < 2; mt++)
#pragma unroll
        for (int nt = 0; nt < 4; nt++)
#pragma unroll
            for (int r = 0; r < 4; r++) acc[mt][nt][r] = 0.f;

    for (int k0 = 0; k0 < FIN; k0 += KC) {
        __syncthreads();
        // stage A chunk (64 x 32 fp32), split hi/lo
#pragma unroll
        for (int it = 0; it < 2; it++) {
            int i = tid + it * 256;                 // 0..511 float4s
            int r = i >> 3, c4 = (i & 7) << 2;
            float4 v = *(const float4*)(A + (size_t)(rowBase + r) * FIN + k0 + c4);
            float xs[4] = {v.x, v.y, v.z, v.w};
#pragma unroll
            for (int c = 0; c < 4; c++) {
                __nv_bfloat16 h = __float2bfloat16(xs[c]);
                Ah[r][c4 + c] = h;
                Al[r][c4 + c] = __float2bfloat16(xs[c] - __bfloat162float(h));
            }
        }
        // stage B chunk: W[k][n] -> Bs[n][k], split hi/lo
#pragma unroll
        for (int it = 0; it < 4; it++) {
            int i = tid + it * 256;
            int kr = i >> 5, n4 = (i & 31) << 2;
            float4 v = *(const float4*)(W + (size_t)(k0 + kr) * OCOLS + colBase + n4);
            float xs[4] = {v.x, v.y, v.z, v.w};
#pragma unroll
            for (int c = 0; c < 4; c++) {
                __nv_bfloat16 h = __float2bfloat16(xs[c]);
                Bh[n4 + c][kr] = h;
                Bl[n4 + c][kr] = __float2bfloat16(xs[c] - __bfloat162float(h));
            }
        }
        __syncthreads();

#pragma unroll
        for (int ks = 0; ks < 2; ks++) {
            const int kk = ks << 4;
            uint32_t ah[2][4], al[2][4], bb[4][2];
#pragma unroll
            for (int mt = 0; mt < 2; mt++) {
                int r0 = wm * 32 + mt * 16 + g;
                ah[mt][0] = *(const uint32_t*)&Ah[r0][kk + tg * 2];
                ah[mt][1] = *(const uint32_t*)&Ah[r0 + 8][kk + tg * 2];
                ah[mt][2] = *(const uint32_t*)&Ah[r0][kk + 8 + tg * 2];
                ah[mt][3] = *(const uint32_t*)&Ah[r0 + 8][kk + 8 + tg * 2];
                al[mt][0] = *(const uint32_t*)&Al[r0][kk + tg * 2];
                al[mt][1] = *(const uint32_t*)&Al[r0 + 8][kk + tg * 2];
                al[mt][2] = *(const uint32_t*)&Al[r0][kk + 8 + tg * 2];
                al[mt][3] = *(const uint32_t*)&Al[r0 + 8][kk + 8 + tg * 2];
            }
#pragma unroll
            for (int nt = 0; nt < 4; nt++) {
                int n0 = wn * 32 + nt * 8 + g;
                bb[nt][0] = *(const uint32_t*)&Bh[n0][kk + tg * 2];
                bb[nt][1] = *(const uint32_t*)&Bh[n0][kk + 8 + tg * 2];
            }
#pragma unroll
            for (int mt = 0; mt < 2; mt++)
#pragma unroll
                for (int nt = 0; nt < 4; nt++) {
                    MMA_BF16(acc[mt][nt], ah[mt], bb[nt]);   // hi*hi
                    MMA_BF16(acc[mt][nt], al[mt], bb[nt]);   // lo*hi
                }
#pragma unroll
            for (int nt = 0; nt < 4; nt++) {
                int n0 = wn * 32 + nt * 8 + g;
                bb[nt][0] = *(const uint32_t*)&Bl[n0][kk + tg * 2];
                bb[nt][1] = *(const uint32_t*)&Bl[n0][kk + 8 + tg * 2];
            }
#pragma unroll
            for (int mt = 0; mt < 2; mt++)
#pragma unroll
                for (int nt = 0; nt < 4; nt++)
                    MMA_BF16(acc[mt][nt], ah[mt], bb[nt]);   // hi*lo
        }
    }

#pragma unroll
    for (int mt = 0; mt < 2; mt++) {
        int r0 = rowBase + wm * 32 + mt * 16 + g;
#pragma unroll
        for (int nt = 0; nt < 4; nt++) {
            int c0 = colBase + wn * 32 + nt * 8 + tg * 2;
            *(float2*)(g_buf + (size_t)r0 * OCOLS + c0) =
                make_float2(acc[mt][nt][0], acc[mt][nt][1]);
            *(float2*)(g_buf + (size_t)(r0 + 8) * OCOLS + c0) =
                make_float2(acc[mt][nt][2], acc[mt][nt][3]);
        }
    }
}

// ---------------- kernel 2: s_src, s_dst  ([bh][n] layout) ----------------
__global__ __launch_bounds__(256) void score_k(const float* __restrict__ attn_w) {
    int w = threadIdx.x >> 5, lane = threadIdx.x & 31;
    int m = blockIdx.x * 8 + w;
    int b = m >> 10, i = m & 1023;
    float ws = attn_w[lane];
    float wd = attn_w[32 + lane];
    const float* gr = g_buf + (size_t)m * OCOLS;
#pragma unroll
    for (int h = 0; h < NH; h++) {
        float gv = gr[h * ND + lane];
        float a = gv * ws, bq = gv * wd;
#pragma unroll
        for (int o = 16; o > 0; o >>= 1) {
            a += __shfl_xor_sync(0xffffffffu, a, o);
            bq += __shfl_xor_sync(0xffffffffu, bq, o);
        }
        if (lane == 0) {
            ssrc_buf[(b * NH + h) * N_ + i] = a;
            sdst_buf[(b * NH + h) * N_ + i] = bq;
        }
    }
}

// ---------------- kernel 3: sort + scalar scans + chunk bases ----------------
__device__ __forceinline__ void warp_passes(float& v, int& id, int k, int jmax, int tid) {
    for (int j = jmax; j > 0; j >>= 1) {
        float pv = __shfl_xor_sync(0xffffffffu, v, j);
        int pid = __shfl_xor_sync(0xffffffffu, id, j);
        bool lower = ((tid & j) == 0);
        bool up = ((tid & k) == 0);
        bool keepmin = (lower == up);
        bool sw = keepmin ? (v > pv) : (v < pv);
        if (sw) { v = pv; id = pid; }
    }
}

__global__ __launch_bounds__(1024) void prep_k() {
    __shared__ float sv[1024];
    __shared__ int   sid[1024];
    __shared__ float e1s[1024];
    __shared__ float e2s[1024];
    __shared__ float wt[32], wo[32], wt2[32], wo2[32];
    __shared__ float tot1[32][33];
    __shared__ float tot2[32][33];

    int bh = blockIdx.x;
    int b = bh >> 3, h = bh & 7;
    int tid = threadIdx.x;
    int w = tid >> 5, lane = tid & 31;

    float rv = sdst_buf[(size_t)bh * N_ + tid];
    int rid = tid;

#pragma unroll
    for (int k = 2; k <= 32; k <<= 1) warp_passes(rv, rid, k, k >> 1, tid);
    sv[tid] = rv; sid[tid] = rid;
    __syncthreads();
    for (int k = 64; k <= 1024; k <<= 1) {
        for (int j = k >> 1; j >= 32; j >>= 1) {
            int ixj = tid ^ j;
            if (ixj > tid) {
                bool up = ((tid & k) == 0);
                float a = sv[tid], c = sv[ixj];
                bool sw = up ? (a > c) : (a < c);
                if (sw) {
                    sv[tid] = c; sv[ixj] = a;
                    int t_ = sid[tid]; sid[tid] = sid[ixj]; sid[ixj] = t_;
                }
            }
            __syncthreads();
        }
        rv = sv[tid]; rid = sid[tid];
        warp_passes(rv, rid, k, 16, tid);
        sv[tid] = rv; sid[tid] = rid;
        __syncthreads();
    }

    vsort_buf[(size_t)bh * N_ + tid] = rv;
    sid_buf[(size_t)bh * N_ + tid] = sid[tid];
    float x1 = __expf(rv);
    float x2 = __expf(0.2f * rv);
    e1s[tid] = x1; e2s[tid] = x2;

    // scalar scans
    float s2 = x2;
#pragma unroll
    for (int o = 1; o < 32; o <<= 1) {
        float y = __shfl_up_sync(0xffffffffu, s2, o);
        if (lane >= o) s2 += y;
    }
    if (lane == 31) wt2[w] = s2;
    float s1 = x1;
#pragma unroll
    for (int o = 1; o < 32; o <<= 1) {
        float y = __shfl_down_sync(0xffffffffu, s1, o);
        if (lane + o < 32) s1 += y;
    }
    if (lane == 0) wt[w] = s1;
    __syncthreads();
    if (w == 0) {
        float t = wt[lane];
        float ts = t;
#pragma unroll
        for (int o = 1; o < 32; o <<= 1) {
            float y = __shfl_down_sync(0xffffffffu, ts, o);
            if (lane + o < 32) ts += y;
        }
        wo[lane] = ts - t;
        float t2 = wt2[lane];
        float ps = t2;
#pragma unroll
        for (int o = 1; o < 32; o <<= 1) {
            float y = __shfl_up_sync(0xffffffffu, ps, o);
            if (lane >= o) ps += y;
        }
        wo2[lane] = ps - t2;
    }
    __syncthreads();
    c1_buf[(size_t)bh * ROWS + tid] = s1 + wo[w];
    c2_buf[(size_t)bh * ROWS + tid + 1] = s2 + wo2[w];
    if (tid == 0) {
        c1_buf[(size_t)bh * ROWS + 1024] = 0.f;
        c2_buf[(size_t)bh * ROWS] = 0.f;
    }

    // pass 1: vector chunk totals (warp w owns k in [w*32,w*32+32), lane = d)
    const float* gb = g_buf + (size_t)b * N_ * OCOLS + h * ND;
    float t1 = 0.f, t2v = 0.f;
    for (int kk = 0; kk < 32; kk++) {
        int k = (w << 5) + kk;
        int j = sid[k];
        float gv = gb[(size_t)j * OCOLS + lane];
        t1 += e1s[k] * gv;
        t2v += e2s[k] * gv;
    }
    tot1[w][lane] = t1;
    tot2[w][lane] = t2v;
    __syncthreads();
    {
        float a1 = tot1[lane][w];   // chunk = lane, d = w
        float a2 = tot2[lane][w];
        float inc1 = a1;
#pragma unroll
        for (int o = 1; o < 32; o <<= 1) {
            float y = __shfl_down_sync(0xffffffffu, inc1, o);
            if (lane + o < 32) inc1 += y;
        }
        float inc2 = a2;
#pragma unroll
        for (int o = 1; o < 32; o <<= 1) {
            float y = __shfl_up_sync(0xffffffffu, inc2, o);
            if (lane >= o) inc2 += y;
        }
        // store: IS1 (inclusive suffix), EP2 (exclusive prefix)
        cb1_buf[((size_t)bh * 32 + lane) * 32 + w] = inc1;
        cb2_buf[((size_t)bh * 32 + lane) * 32 + w] = inc2 - a2;
    }
}

// ---------------- kernel 3b: merged prefix/suffix writes ----------------
// grid (4, 64), 256 threads = 8 warps; warp wi handles chunk c = bx*8+wi, lane = d.
__global__ __launch_bounds__(256) void write_k() {
    int bh = blockIdx.y;
    int b = bh >> 3, h = bh & 7;
    int wi = threadIdx.x >> 5, lane = threadIdx.x & 31;
    int c = blockIdx.x * 8 + wi;

    float is1 = cb1_buf[((size_t)bh * 32 + c) * 32 + lane];
    float r2  = cb2_buf[((size_t)bh * 32 + c) * 32 + lane];
    const float* gb = g_buf + (size_t)b * N_ * OCOLS + h * ND;
    const int* sidp = sid_buf + (size_t)bh * N_;
    const float* vsp = vsort_buf + (size_t)bh * N_;
    float* S1 = suf1_buf + (size_t)bh * ROWS * ND;
    float* P2 = pre2_buf + (size_t)bh * ROWS * ND;

    if (c == 0) P2[lane] = 0.f;                    // PRE2[0] = 0

    float p1 = 0.f;
#pragma unroll 4
    for (int kk = 0; kk < 32; kk++) {
        int k = (c << 5) + kk;
        int j = sidp[k];
        float v = vsp[k];
        float e1 = __expf(v);
        float e2 = __expf(0.2f * v);
        float gv = gb[(size_t)j * OCOLS + lane];
        S1[(size_t)k * ND + lane] = is1 - p1;      // SUF1[k] = IS1 - prefix_excl
        p1 += e1 * gv;
        r2 += e2 * gv;
        P2[(size_t)(k + 1) * ND + lane] = r2;
    }
    if (c == 31) S1[(size_t)1024 * ND + lane] = 0.f;
}

// ---------------- kernel 4a: per-query scalars (smem search) ----------------
__global__ __launch_bounds__(1024) void qscal_k() {
    __shared__ float vs[1024];
    __shared__ float sc1[ROWS];
    __shared__ float sc2[ROWS];
    int bh = blockIdx.x;
    int tid = threadIdx.x;

    vs[tid] = vsort_buf[(size_t)bh * N_ + tid];
    sc1[tid] = c1_buf[(size_t)bh * ROWS + tid];
    sc2[tid] = c2_buf[(size_t)bh * ROWS + tid];
    if (tid == 0) {
        sc1[1024] = 0.f;
        sc2[1024] = c2_buf[(size_t)bh * ROWS + 1024];
    }
    __syncthreads();

    float src = ssrc_buf[(size_t)bh * N_ + tid];
    float th = -src;
    int lo = 0, hi = 1024;
#pragma unroll
    for (int s = 0; s < 10; s++) {
        int mid = (lo + hi) >> 1;
        if (vs[mid] < th) lo = mid + 1; else hi = mid;
    }
    int t = lo;

    float vmax = vs[1023];
    float etop = src + vmax;
    float mM = (etop >= 0.f) ? etop : 0.2f * etop;
    float E1 = (t < 1024) ? __expf(src - mM) : 0.f;
    float E2 = (t > 0) ? __expf(0.2f * src - mM) : 0.f;

    float rden = 1.f / (E1 * sc1[t] + E2 * sc2[t]);
    qscal_buf[(size_t)bh * N_ + tid] = make_float4(E1 * rden, E2 * rden, __int_as_float(t), 0.f);
}

// ---------------- kernel 4b: output (float4/thread) ----------------
__global__ __launch_bounds__(256) void out_k(float* __restrict__ out) {
    int idx = blockIdx.x * 256 + threadIdx.x;      // 512K threads, 4 floats each
    int e = idx << 2;
    int m = e >> 8, cc = e & 255;
    int h = cc >> 5, d0 = cc & 31;
    int b = m >> 10, i = m & 1023;
    int bh = b * NH + h;
    float4 s = qscal_buf[(size_t)bh * N_ + i];
    int t = __float_as_int(s.z);
    size_t base = ((size_t)bh * ROWS + t) * ND + d0;
    float4 sf = *(const float4*)(suf1_buf + base);
    float4 pf = *(const float4*)(pre2_buf + base);
    float4 o;
    o.x = s.x * sf.x + s.y * pf.x;
    o.y = s.x * sf.y + s.y * pf.y;
    o.z = s.x * sf.z + s.y * pf.z;
    o.w = s.x * sf.w + s.y * pf.w;
    *(float4*)(out + e) = o;
}

// ---------------- launcher ----------------
extern "C" void kernel_launch(void* const* d_in, const int* in_sizes, int n_in,
                              void* d_out, int out_size) {
    const float* vertex = (const float*)d_in[0];
    const float* w_vert = (const float*)d_in[1];
    const float* attn_w = (const float*)d_in[2];
    float* out = (float*)d_out;

    dim3 gG(2, 128);
    gemm_mma_k<<<gG, 256>>>(vertex, w_vert);
    score_k<<<M_TOT / 8, 256>>>(attn_w);
    prep_k<<<NBH, 1024>>>();
    write_k<<<dim3(4, NBH), 256>>>();
    qscal_k<<<NBH, 1024>>>();
    out_k<<<M_TOT * OCOLS / 4 / 256, 256>>>(out);
}

// round 5
// speedup vs baseline: 1.1494x; 1.1494x over previous
#include <cuda_runtime.h>
#include <cuda_bf16.h>
#include <cstdint>

// Problem constants
#define B_    8
#define N_    1024
#define FIN   256
#define NH    8
#define ND    32
#define M_TOT (B_ * N_)      // 8192
#define NBH   (B_ * NH)      // 64
#define ROWS  1025
#define OCOLS (NH * ND)      // 256

// ---------------- scratch ----------------
__device__ float g_buf[M_TOT * OCOLS];        // g[m][h*32+d] fp32
__device__ float ssrc_buf[NBH * N_];          // [bh][n]
__device__ float sdst_buf[NBH * N_];          // [bh][n]
__device__ float vsort_buf[NBH * N_];
__device__ int   sid_buf[NBH * N_];
__device__ float e1_buf[NBH * N_];            // exp(v_k) at sorted position k
__device__ float e2_buf[NBH * N_];            // exp(0.2 v_k)
__device__ float suf1_buf[NBH * ROWS * ND];
__device__ float pre2_buf[NBH * ROWS * ND];
__device__ float c1_buf[NBH * ROWS];
__device__ float c2_buf[NBH * ROWS];
__device__ float cb1_buf[NBH * 32 * 32];      // [bh][chunk][d]: inclusive-suffix base
__device__ float cb2_buf[NBH * 32 * 32];      // [bh][chunk][d]: exclusive-prefix base
__device__ float4 qscal_buf[NBH * N_];        // [bh][n]: {E1/den, E2/den, bits(t), 0}

// ---------------- mma.sync helper ----------------
#define MMA_BF16(d, a, b)                                                      \
    asm volatile("mma.sync.aligned.m16n8k16.row.col.f32.bf16.bf16.f32 "        \
        "{%0,%1,%2,%3}, {%4,%5,%6,%7}, {%8,%9}, {%0,%1,%2,%3};"                \
        : "+f"((d)[0]), "+f"((d)[1]), "+f"((d)[2]), "+f"((d)[3])               \
        : "r"((a)[0]), "r"((a)[1]), "r"((a)[2]), "r"((a)[3]),                  \
          "r"((b)[0]), "r"((b)[1]))

// ---------------- kernel 1: g = vertex @ w_vert via HMMA bf16 hi/lo,
//                  fused s_src/s_dst epilogue ----------------
// Tile 64m x 128n, grid (2, 128), 8 warps (2m x 4n), warp tile 32x32 = 1 head.
#define KC 32
#define APAD 8
__global__ __launch_bounds__(256) void gemm_mma_k(const float* __restrict__ A,
                                                  const float* __restrict__ W,
                                                  const float* __restrict__ attn_w) {
    __shared__ __align__(16) __nv_bfloat16 Ah[64][KC + APAD];
    __shared__ __align__(16) __nv_bfloat16 Al[64][KC + APAD];
    __shared__ __align__(16) __nv_bfloat16 Bh[128][KC + APAD];
    __shared__ __align__(16) __nv_bfloat16 Bl[128][KC + APAD];

    const int tid = threadIdx.x;
    const int wid = tid >> 5, lane = tid & 31;
    const int wm = wid >> 2, wn = wid & 3;
    const int rowBase = blockIdx.y * 64;
    const int colBase = blockIdx.x * 128;
    const int g = lane >> 2, tg = lane & 3;

    float acc[2][4][4];
#pragma unroll
    for (int mt = 0; mt < 2; mt++)
#pragma unroll
        for (int nt = 0; nt < 4; nt++)
#pragma unroll
            for (int r = 0; r < 4; r++) acc[mt][nt][r] = 0.f;

    for (int k0 = 0; k0 < FIN; k0 += KC) {
        __syncthreads();
#pragma unroll
        for (int it = 0; it < 2; it++) {
            int i = tid + it * 256;
            int r = i >> 3, c4 = (i & 7) << 2;
            float4 v = *(const float4*)(A + (size_t)(rowBase + r) * FIN + k0 + c4);
            float xs[4] = {v.x, v.y, v.z, v.w};
#pragma unroll
            for (int c = 0; c < 4; c++) {
                __nv_bfloat16 h = __float2bfloat16(xs[c]);
                Ah[r][c4 + c] = h;
                Al[r][c4 + c] = __float2bfloat16(xs[c] - __bfloat162float(h));
            }
        }
#pragma unroll
        for (int it = 0; it < 4; it++) {
            int i = tid + it * 256;
            int kr = i >> 5, n4 = (i & 31) << 2;
            float4 v = *(const float4*)(W + (size_t)(k0 + kr) * OCOLS + colBase + n4);
            float xs[4] = {v.x, v.y, v.z, v.w};
#pragma unroll
            for (int c = 0; c < 4; c++) {
                __nv_bfloat16 h = __float2bfloat16(xs[c]);
                Bh[n4 + c][kr] = h;
                Bl[n4 + c][kr] = __float2bfloat16(xs[c] - __bfloat162float(h));
            }
        }
        __syncthreads();

#pragma unroll
        for (int ks = 0; ks < 2; ks++) {
            const int kk = ks << 4;
            uint32_t ah[2][4], al[2][4], bb[4][2];
#pragma unroll
            for (int mt = 0; mt < 2; mt++) {
                int r0 = wm * 32 + mt * 16 + g;
                ah[mt][0] = *(const uint32_t*)&Ah[r0][kk + tg * 2];
                ah[mt][1] = *(const uint32_t*)&Ah[r0 + 8][kk + tg * 2];
                ah[mt][2] = *(const uint32_t*)&Ah[r0][kk + 8 + tg * 2];
                ah[mt][3] = *(const uint32_t*)&Ah[r0 + 8][kk + 8 + tg * 2];
                al[mt][0] = *(const uint32_t*)&Al[r0][kk + tg * 2];
                al[mt][1] = *(const uint32_t*)&Al[r0 + 8][kk + tg * 2];
                al[mt][2] = *(const uint32_t*)&Al[r0][kk + 8 + tg * 2];
                al[mt][3] = *(const uint32_t*)&Al[r0 + 8][kk + 8 + tg * 2];
            }
#pragma unroll
            for (int nt = 0; nt < 4; nt++) {
                int n0 = wn * 32 + nt * 8 + g;
                bb[nt][0] = *(const uint32_t*)&Bh[n0][kk + tg * 2];
                bb[nt][1] = *(const uint32_t*)&Bh[n0][kk + 8 + tg * 2];
            }
#pragma unroll
            for (int mt = 0; mt < 2; mt++)
#pragma unroll
                for (int nt = 0; nt < 4; nt++) {
                    MMA_BF16(acc[mt][nt], ah[mt], bb[nt]);   // hi*hi
                    MMA_BF16(acc[mt][nt], al[mt], bb[nt]);   // lo*hi
                }
#pragma unroll
            for (int nt = 0; nt < 4; nt++) {
                int n0 = wn * 32 + nt * 8 + g;
                bb[nt][0] = *(const uint32_t*)&Bl[n0][kk + tg * 2];
                bb[nt][1] = *(const uint32_t*)&Bl[n0][kk + 8 + tg * 2];
            }
#pragma unroll
            for (int mt = 0; mt < 2; mt++)
#pragma unroll
                for (int nt = 0; nt < 4; nt++)
                    MMA_BF16(acc[mt][nt], ah[mt], bb[nt]);   // hi*lo
        }
    }

    // epilogue: write g
#pragma unroll
    for (int mt = 0; mt < 2; mt++) {
        int r0 = rowBase + wm * 32 + mt * 16 + g;
#pragma unroll
        for (int nt = 0; nt < 4; nt++) {
            int c0 = colBase + wn * 32 + nt * 8 + tg * 2;
            *(float2*)(g_buf + (size_t)r0 * OCOLS + c0) =
                make_float2(acc[mt][nt][0], acc[mt][nt][1]);
            *(float2*)(g_buf + (size_t)(r0 + 8) * OCOLS + c0) =
                make_float2(acc[mt][nt][2], acc[mt][nt][3]);
        }
    }

    // fused score: this warp's 32 cols = head hh
    {
        float ws[4][2], wd[4][2];
#pragma unroll
        for (int nt = 0; nt < 4; nt++)
#pragma unroll
            for (int j = 0; j < 2; j++) {
                int d = nt * 8 + tg * 2 + j;
                ws[nt][j] = attn_w[d];
                wd[nt][j] = attn_w[32 + d];
            }
        int hh = blockIdx.x * 4 + wn;
#pragma unroll
        for (int mt = 0; mt < 2; mt++)
#pragma unroll
            for (int rh = 0; rh < 2; rh++) {
                float as = 0.f, ad = 0.f;
#pragma unroll
                for (int nt = 0; nt < 4; nt++) {
                    as += acc[mt][nt][rh * 2] * ws[nt][0] + acc[mt][nt][rh * 2 + 1] * ws[nt][1];
                    ad += acc[mt][nt][rh * 2] * wd[nt][0] + acc[mt][nt][rh * 2 + 1] * wd[nt][1];
                }
                as += __shfl_xor_sync(0xffffffffu, as, 1);
                as += __shfl_xor_sync(0xffffffffu, as, 2);
                ad += __shfl_xor_sync(0xffffffffu, ad, 1);
                ad += __shfl_xor_sync(0xffffffffu, ad, 2);
                if (tg == 0) {
                    int m = rowBase + wm * 32 + mt * 16 + rh * 8 + g;
                    int b = m >> 10, i = m & 1023;
                    ssrc_buf[(size_t)(b * NH + hh) * N_ + i] = as;
                    sdst_buf[(size_t)(b * NH + hh) * N_ + i] = ad;
                }
            }
    }
}

// ---------------- kernel 3: sort (packed u32) + scalar scans + chunk bases ----------------
__device__ __forceinline__ void warp_passes_u(uint32_t& key, int k, int jmax, int tid) {
    for (int j = jmax; j > 0; j >>= 1) {
        uint32_t pk = __shfl_xor_sync(0xffffffffu, key, j);
        bool lower = ((tid & j) == 0);
        bool up = ((tid & k) == 0);
        bool keepmin = (lower == up);
        bool sw = keepmin ? (key > pk) : (key < pk);
        if (sw) key = pk;
    }
}

__global__ __launch_bounds__(1024) void prep_k() {
    __shared__ uint32_t su[1024];
    __shared__ float e1s[1024];
    __shared__ float e2s[1024];
    __shared__ float wt[32], wo[32], wt2[32], wo2[32];
    __shared__ float tot1[32][33];
    __shared__ float tot2[32][33];

    int bh = blockIdx.x;
    int b = bh >> 3, h = bh & 7;
    int tid = threadIdx.x;
    int w = tid >> 5, lane = tid & 31;

    float v0 = sdst_buf[(size_t)bh * N_ + tid];
    uint32_t u = __float_as_uint(v0);
    u = (u & 0x80000000u) ? ~u : (u | 0x80000000u);   // order-preserving
    uint32_t key = (u & 0xFFFFFC00u) | (uint32_t)tid;

#pragma unroll
    for (int k = 2; k <= 32; k <<= 1) warp_passes_u(key, k, k >> 1, tid);
    su[tid] = key;
    __syncthreads();
    for (int k = 64; k <= 1024; k <<= 1) {
        for (int j = k >> 1; j >= 32; j >>= 1) {
            int ixj = tid ^ j;
            if (ixj > tid) {
                bool up = ((tid & k) == 0);
                uint32_t a = su[tid], c = su[ixj];
                bool sw = up ? (a > c) : (a < c);
                if (sw) { su[tid] = c; su[ixj] = a; }
            }
            __syncthreads();
        }
        key = su[tid];
        warp_passes_u(key, k, 16, tid);
        su[tid] = key;
        __syncthreads();
    }

    int idj = (int)(key & 1023u);
    float rv = sdst_buf[(size_t)bh * N_ + idj];       // exact value
    vsort_buf[(size_t)bh * N_ + tid] = rv;
    sid_buf[(size_t)bh * N_ + tid] = idj;
    float x1 = __expf(rv);
    float x2 = __expf(0.2f * rv);
    e1s[tid] = x1; e2s[tid] = x2;
    e1_buf[(size_t)bh * N_ + tid] = x1;
    e2_buf[(size_t)bh * N_ + tid] = x2;

    // scalar scans
    float s2 = x2;
#pragma unroll
    for (int o = 1; o < 32; o <<= 1) {
        float y = __shfl_up_sync(0xffffffffu, s2, o);
        if (lane >= o) s2 += y;
    }
    if (lane == 31) wt2[w] = s2;
    float s1 = x1;
#pragma unroll
    for (int o = 1; o < 32; o <<= 1) {
        float y = __shfl_down_sync(0xffffffffu, s1, o);
        if (lane + o < 32) s1 += y;
    }
    if (lane == 0) wt[w] = s1;
    __syncthreads();
    if (w == 0) {
        float t = wt[lane];
        float ts = t;
#pragma unroll
        for (int o = 1; o < 32; o <<= 1) {
            float y = __shfl_down_sync(0xffffffffu, ts, o);
            if (lane + o < 32) ts += y;
        }
        wo[lane] = ts - t;
        float t2 = wt2[lane];
        float ps = t2;
#pragma unroll
        for (int o = 1; o < 32; o <<= 1) {
            float y = __shfl_up_sync(0xffffffffu, ps, o);
            if (lane >= o) ps += y;
        }
        wo2[lane] = ps - t2;
    }
    __syncthreads();
    c1_buf[(size_t)bh * ROWS + tid] = s1 + wo[w];
    c2_buf[(size_t)bh * ROWS + tid + 1] = s2 + wo2[w];
    if (tid == 0) {
        c1_buf[(size_t)bh * ROWS + 1024] = 0.f;
        c2_buf[(size_t)bh * ROWS] = 0.f;
    }

    // vector chunk totals (warp w owns k in [w*32,w*32+32), lane = d)
    const float* gb = g_buf + (size_t)b * N_ * OCOLS + h * ND;
    float t1 = 0.f, t2v = 0.f;
    for (int kk = 0; kk < 32; kk++) {
        int k = (w << 5) + kk;
        int j = (int)(su[k] & 1023u);
        float gv = gb[(size_t)j * OCOLS + lane];
        t1 += e1s[k] * gv;
        t2v += e2s[k] * gv;
    }
    tot1[w][lane] = t1;
    tot2[w][lane] = t2v;
    __syncthreads();
    {
        float a1 = tot1[lane][w];   // chunk = lane, d = w
        float a2 = tot2[lane][w];
        float inc1 = a1;
#pragma unroll
        for (int o = 1; o < 32; o <<= 1) {
            float y = __shfl_down_sync(0xffffffffu, inc1, o);
            if (lane + o < 32) inc1 += y;
        }
        float inc2 = a2;
#pragma unroll
        for (int o = 1; o < 32; o <<= 1) {
            float y = __shfl_up_sync(0xffffffffu, inc2, o);
            if (lane >= o) inc2 += y;
        }
        cb1_buf[((size_t)bh * 32 + lane) * 32 + w] = inc1;        // inclusive suffix
        cb2_buf[((size_t)bh * 32 + lane) * 32 + w] = inc2 - a2;   // exclusive prefix
    }
}

// ---------------- kernel 3b: merged prefix/suffix writes (full prefetch) ----------------
// grid (4, 64), 256 threads; warp wi handles chunk c = bx*8+wi, lane = d.
__global__ __launch_bounds__(256, 2) void write_k() {
    int bh = blockIdx.y;
    int b = bh >> 3, h = bh & 7;
    int wi = threadIdx.x >> 5, lane = threadIdx.x & 31;
    int c = blockIdx.x * 8 + wi;
    int k0 = c << 5;

    float is1 = cb1_buf[((size_t)bh * 32 + c) * 32 + lane];
    float r2  = cb2_buf[((size_t)bh * 32 + c) * 32 + lane];
    const float* gb = g_buf + (size_t)b * N_ * OCOLS + h * ND;
    const int* sidp = sid_buf + (size_t)bh * N_ + k0;
    const float* e1p = e1_buf + (size_t)bh * N_ + k0;
    const float* e2p = e2_buf + (size_t)bh * N_ + k0;
    float* S1 = suf1_buf + (size_t)bh * ROWS * ND;
    float* P2 = pre2_buf + (size_t)bh * ROWS * ND;

    if (c == 0) P2[lane] = 0.f;

    // prefetch all 32 gathers (MLP 32)
    float gv[32];
#pragma unroll
    for (int kk = 0; kk < 32; kk++)
        gv[kk] = gb[(size_t)sidp[kk] * OCOLS + lane];

    float p1 = 0.f;
#pragma unroll
    for (int kk = 0; kk < 32; kk++) {
        int k = k0 + kk;
        S1[(size_t)k * ND + lane] = is1 - p1;
        p1 = fmaf(e1p[kk], gv[kk], p1);
        r2 = fmaf(e2p[kk], gv[kk], r2);
        P2[(size_t)(k + 1) * ND + lane] = r2;
    }
    if (c == 31) S1[(size_t)1024 * ND + lane] = 0.f;
}

// ---------------- kernel 4a: per-query scalars (smem search) ----------------
__global__ __launch_bounds__(1024) void qscal_k() {
    __shared__ float vs[1024];
    __shared__ float sc1[ROWS];
    __shared__ float sc2[ROWS];
    int bh = blockIdx.x;
    int tid = threadIdx.x;

    vs[tid] = vsort_buf[(size_t)bh * N_ + tid];
    sc1[tid] = c1_buf[(size_t)bh * ROWS + tid];
    sc2[tid] = c2_buf[(size_t)bh * ROWS + tid];
    if (tid == 0) {
        sc1[1024] = 0.f;
        sc2[1024] = c2_buf[(size_t)bh * ROWS + 1024];
    }
    __syncthreads();

    float src = ssrc_buf[(size_t)bh * N_ + tid];
    float th = -src;
    int lo = 0, hi = 1024;
#pragma unroll
    for (int s = 0; s < 10; s++) {
        int mid = (lo + hi) >> 1;
        if (vs[mid] < th) lo = mid + 1; else hi = mid;
    }
    int t = lo;

    float vmax = vs[1023];
    float etop = src + vmax;
    float mM = (etop >= 0.f) ? etop : 0.2f * etop;
    float E1 = (t < 1024) ? __expf(src - mM) : 0.f;
    float E2 = (t > 0) ? __expf(0.2f * src - mM) : 0.f;

    float rden = 1.f / (E1 * sc1[t] + E2 * sc2[t]);
    qscal_buf[(size_t)bh * N_ + tid] = make_float4(E1 * rden, E2 * rden, __int_as_float(t), 0.f);
}

// ---------------- kernel 4b: output (float4/thread) ----------------
__global__ __launch_bounds__(256) void out_k(float* __restrict__ out) {
    int idx = blockIdx.x * 256 + threadIdx.x;
    int e = idx << 2;
    int m = e >> 8, cc = e & 255;
    int h = cc >> 5, d0 = cc & 31;
    int b = m >> 10, i = m & 1023;
    int bh = b * NH + h;
    float4 s = qscal_buf[(size_t)bh * N_ + i];
    int t = __float_as_int(s.z);
    size_t base = ((size_t)bh * ROWS + t) * ND + d0;
    float4 sf = *(const float4*)(suf1_buf + base);
    float4 pf = *(const float4*)(pre2_buf + base);
    float4 o;
    o.x = s.x * sf.x + s.y * pf.x;
    o.y = s.x * sf.y + s.y * pf.y;
    o.z = s.x * sf.z + s.y * pf.z;
    o.w = s.x * sf.w + s.y * pf.w;
    *(float4*)(out + e) = o;
}

// ---------------- launcher ----------------
extern "C" void kernel_launch(void* const* d_in, const int* in_sizes, int n_in,
                              void* d_out, int out_size) {
    const float* vertex = (const float*)d_in[0];
    const float* w_vert = (const float*)d_in[1];
    const float* attn_w = (const float*)d_in[2];
    float* out = (float*)d_out;

    dim3 gG(2, 128);
    gemm_mma_k<<<gG, 256>>>(vertex, w_vert, attn_w);
    prep_k<<<NBH, 1024>>>();
    write_k<<<dim3(4, NBH), 256>>>();
    qscal_k<<<NBH, 1024>>>();
    out_k<<<M_TOT * OCOLS / 4 / 256, 256>>>(out);
}

// round 6
// speedup vs baseline: 1.1765x; 1.0236x over previous
#include <cuda_runtime.h>
#include <cuda_bf16.h>
#include <cstdint>

// Problem constants
#define B_    8
#define N_    1024
#define FIN   256
#define NH    8
#define ND    32
#define M_TOT (B_ * N_)      // 8192
#define NBH   (B_ * NH)      // 64
#define ROWS  1025
#define OCOLS (NH * ND)      // 256

// ---------------- scratch ----------------
__device__ float g_buf[M_TOT * OCOLS];        // g[m][h*32+d] fp32
__device__ float ssrc_buf[NBH * N_];          // [bh][n]
__device__ float sdst_buf[NBH * N_];          // [bh][n]
__device__ int   sid_buf[NBH * N_];
__device__ float e1_buf[NBH * N_];            // exp(v_k) at sorted position k
__device__ float e2_buf[NBH * N_];            // exp(0.2 v_k)
__device__ float suf1_buf[NBH * ROWS * ND];
__device__ float pre2_buf[NBH * ROWS * ND];
__device__ float cb1_buf[NBH * 32 * 32];      // [bh][chunk][d]: inclusive-suffix base
__device__ float cb2_buf[NBH * 32 * 32];      // [bh][chunk][d]: exclusive-prefix base
__device__ float4 qscal_buf[NBH * N_];        // [bh][n]: {E1/den, E2/den, bits(t), 0}

// ---------------- mma.sync helper ----------------
#define MMA_BF16(d, a, b)                                                      \
    asm volatile("mma.sync.aligned.m16n8k16.row.col.f32.bf16.bf16.f32 "        \
        "{%0,%1,%2,%3}, {%4,%5,%6,%7}, {%8,%9}, {%0,%1,%2,%3};"                \
        : "+f"((d)[0]), "+f"((d)[1]), "+f"((d)[2]), "+f"((d)[3])               \
        : "r"((a)[0]), "r"((a)[1]), "r"((a)[2]), "r"((a)[3]),                  \
          "r"((b)[0]), "r"((b)[1]))

// ---------------- kernel 1: g = vertex @ w_vert via HMMA bf16 hi/lo,
//                  fused s_src/s_dst epilogue, reg-prefetch pipeline ----------------
// Tile 64m x 128n, grid (2, 128), 8 warps (2m x 4n), warp tile 32x32 = 1 head.
#define KC 32
#define APAD 8
__global__ __launch_bounds__(256) void gemm_mma_k(const float* __restrict__ A,
                                                  const float* __restrict__ W,
                                                  const float* __restrict__ attn_w) {
    __shared__ __align__(16) __nv_bfloat16 Ah[64][KC + APAD];
    __shared__ __align__(16) __nv_bfloat16 Al[64][KC + APAD];
    __shared__ __align__(16) __nv_bfloat16 Bh[128][KC + APAD];
    __shared__ __align__(16) __nv_bfloat16 Bl[128][KC + APAD];

    const int tid = threadIdx.x;
    const int wid = tid >> 5, lane = tid & 31;
    const int wm = wid >> 2, wn = wid & 3;
    const int rowBase = blockIdx.y * 64;
    const int colBase = blockIdx.x * 128;
    const int g = lane >> 2, tg = lane & 3;

    // staging coords
    const int ar0 = tid >> 3, ac4 = (tid & 7) << 2;           // A it=0: rows 0..31
    const int ar1 = (tid + 256) >> 3;                          // A it=1: rows 32..63
    const int bk0 = tid >> 5, bn4 = (tid & 31) << 2;           // B it: kr = bk0 + it*8

    float acc[2][4][4];
#pragma unroll
    for (int mt = 0; mt < 2; mt++)
#pragma unroll
        for (int nt = 0; nt < 4; nt++)
#pragma unroll
            for (int r = 0; r < 4; r++) acc[mt][nt][r] = 0.f;

    float4 pa[2], pb[4];
    // prefetch chunk 0
    pa[0] = *(const float4*)(A + (size_t)(rowBase + ar0) * FIN + ac4);
    pa[1] = *(const float4*)(A + (size_t)(rowBase + ar1) * FIN + ac4);
#pragma unroll
    for (int it = 0; it < 4; it++)
        pb[it] = *(const float4*)(W + (size_t)(bk0 + it * 8) * OCOLS + colBase + bn4);

    for (int kc = 0; kc < 8; kc++) {
        __syncthreads();
        // store staged regs -> smem with hi/lo split
#pragma unroll
        for (int it = 0; it < 2; it++) {
            int r = (it == 0) ? ar0 : ar1;
            float xs[4] = {pa[it].x, pa[it].y, pa[it].z, pa[it].w};
#pragma unroll
            for (int c = 0; c < 4; c++) {
                __nv_bfloat16 h = __float2bfloat16(xs[c]);
                Ah[r][ac4 + c] = h;
                Al[r][ac4 + c] = __float2bfloat16(xs[c] - __bfloat162float(h));
            }
        }
#pragma unroll
        for (int it = 0; it < 4; it++) {
            int kr = bk0 + it * 8;
            float xs[4] = {pb[it].x, pb[it].y, pb[it].z, pb[it].w};
#pragma unroll
            for (int c = 0; c < 4; c++) {
                __nv_bfloat16 h = __float2bfloat16(xs[c]);
                Bh[bn4 + c][kr] = h;
                Bl[bn4 + c][kr] = __float2bfloat16(xs[c] - __bfloat162float(h));
            }
        }
        __syncthreads();

        // prefetch next chunk (overlaps with mma below)
        if (kc < 7) {
            int k0 = (kc + 1) * KC;
            pa[0] = *(const float4*)(A + (size_t)(rowBase + ar0) * FIN + k0 + ac4);
            pa[1] = *(const float4*)(A + (size_t)(rowBase + ar1) * FIN + k0 + ac4);
#pragma unroll
            for (int it = 0; it < 4; it++)
                pb[it] = *(const float4*)(W + (size_t)(k0 + bk0 + it * 8) * OCOLS + colBase + bn4);
        }

#pragma unroll
        for (int ks = 0; ks < 2; ks++) {
            const int kk = ks << 4;
            uint32_t ah[2][4], al[2][4], bb[4][2];
#pragma unroll
            for (int mt = 0; mt < 2; mt++) {
                int r0 = wm * 32 + mt * 16 + g;
                ah[mt][0] = *(const uint32_t*)&Ah[r0][kk + tg * 2];
                ah[mt][1] = *(const uint32_t*)&Ah[r0 + 8][kk + tg * 2];
                ah[mt][2] = *(const uint32_t*)&Ah[r0][kk + 8 + tg * 2];
                ah[mt][3] = *(const uint32_t*)&Ah[r0 + 8][kk + 8 + tg * 2];
                al[mt][0] = *(const uint32_t*)&Al[r0][kk + tg * 2];
                al[mt][1] = *(const uint32_t*)&Al[r0 + 8][kk + tg * 2];
                al[mt][2] = *(const uint32_t*)&Al[r0][kk + 8 + tg * 2];
                al[mt][3] = *(const uint32_t*)&Al[r0 + 8][kk + 8 + tg * 2];
            }
#pragma unroll
            for (int nt = 0; nt < 4; nt++) {
                int n0 = wn * 32 + nt * 8 + g;
                bb[nt][0] = *(const uint32_t*)&Bh[n0][kk + tg * 2];
                bb[nt][1] = *(const uint32_t*)&Bh[n0][kk + 8 + tg * 2];
            }
#pragma unroll
            for (int mt = 0; mt < 2; mt++)
#pragma unroll
                for (int nt = 0; nt < 4; nt++) {
                    MMA_BF16(acc[mt][nt], ah[mt], bb[nt]);   // hi*hi
                    MMA_BF16(acc[mt][nt], al[mt], bb[nt]);   // lo*hi
                }
#pragma unroll
            for (int nt = 0; nt < 4; nt++) {
                int n0 = wn * 32 + nt * 8 + g;
                bb[nt][0] = *(const uint32_t*)&Bl[n0][kk + tg * 2];
                bb[nt][1] = *(const uint32_t*)&Bl[n0][kk + 8 + tg * 2];
            }
#pragma unroll
            for (int mt = 0; mt < 2; mt++)
#pragma unroll
                for (int nt = 0; nt < 4; nt++)
                    MMA_BF16(acc[mt][nt], ah[mt], bb[nt]);   // hi*lo
        }
    }

    // epilogue: write g
#pragma unroll
    for (int mt = 0; mt < 2; mt++) {
        int r0 = rowBase + wm * 32 + mt * 16 + g;
#pragma unroll
        for (int nt = 0; nt < 4; nt++) {
            int c0 = colBase + wn * 32 + nt * 8 + tg * 2;
            *(float2*)(g_buf + (size_t)r0 * OCOLS + c0) =
                make_float2(acc[mt][nt][0], acc[mt][nt][1]);
            *(float2*)(g_buf + (size_t)(r0 + 8) * OCOLS + c0) =
                make_float2(acc[mt][nt][2], acc[mt][nt][3]);
        }
    }

    // fused score
    {
        float ws[4][2], wd[4][2];
#pragma unroll
        for (int nt = 0; nt < 4; nt++)
#pragma unroll
            for (int j = 0; j < 2; j++) {
                int d = nt * 8 + tg * 2 + j;
                ws[nt][j] = attn_w[d];
                wd[nt][j] = attn_w[32 + d];
            }
        int hh = blockIdx.x * 4 + wn;
#pragma unroll
        for (int mt = 0; mt < 2; mt++)
#pragma unroll
            for (int rh = 0; rh < 2; rh++) {
                float as = 0.f, ad = 0.f;
#pragma unroll
                for (int nt = 0; nt < 4; nt++) {
                    as += acc[mt][nt][rh * 2] * ws[nt][0] + acc[mt][nt][rh * 2 + 1] * ws[nt][1];
                    ad += acc[mt][nt][rh * 2] * wd[nt][0] + acc[mt][nt][rh * 2 + 1] * wd[nt][1];
                }
                as += __shfl_xor_sync(0xffffffffu, as, 1);
                as += __shfl_xor_sync(0xffffffffu, as, 2);
                ad += __shfl_xor_sync(0xffffffffu, ad, 1);
                ad += __shfl_xor_sync(0xffffffffu, ad, 2);
                if (tg == 0) {
                    int m = rowBase + wm * 32 + mt * 16 + rh * 8 + g;
                    int b = m >> 10, i = m & 1023;
                    ssrc_buf[(size_t)(b * NH + hh) * N_ + i] = as;
                    sdst_buf[(size_t)(b * NH + hh) * N_ + i] = ad;
                }
            }
    }
}

// ---------------- kernel 2: sort + scans + chunk bases + FUSED query scalars ----------------
__device__ __forceinline__ void warp_passes_u(uint32_t& key, int k, int jmax, int tid) {
    for (int j = jmax; j > 0; j >>= 1) {
        uint32_t pk = __shfl_xor_sync(0xffffffffu, key, j);
        bool lower = ((tid & j) == 0);
        bool up = ((tid & k) == 0);
        bool keepmin = (lower == up);
        bool sw = keepmin ? (key > pk) : (key < pk);
        if (sw) key = pk;
    }
}

__global__ __launch_bounds__(1024) void prep_k() {
    __shared__ uint32_t su[1024];
    __shared__ float vs[1024];
    __shared__ float e1s[1024];
    __shared__ float e2s[1024];
    __shared__ float sc1[ROWS];
    __shared__ float sc2[ROWS];
    __shared__ float wt[32], wo[32], wt2[32], wo2[32];
    __shared__ float tot1[32][33];
    __shared__ float tot2[32][33];

    int bh = blockIdx.x;
    int b = bh >> 3, h = bh & 7;
    int tid = threadIdx.x;
    int w = tid >> 5, lane = tid & 31;

    float v0 = sdst_buf[(size_t)bh * N_ + tid];
    uint32_t u = __float_as_uint(v0);
    u = (u & 0x80000000u) ? ~u : (u | 0x80000000u);   // order-preserving
    uint32_t key = (u & 0xFFFFFC00u) | (uint32_t)tid;

#pragma unroll
    for (int k = 2; k <= 32; k <<= 1) warp_passes_u(key, k, k >> 1, tid);
    su[tid] = key;
    __syncthreads();
    for (int k = 64; k <= 1024; k <<= 1) {
        for (int j = k >> 1; j >= 32; j >>= 1) {
            int ixj = tid ^ j;
            if (ixj > tid) {
                bool up = ((tid & k) == 0);
                uint32_t a = su[tid], c = su[ixj];
                bool sw = up ? (a > c) : (a < c);
                if (sw) { su[tid] = c; su[ixj] = a; }
            }
            __syncthreads();
        }
        key = su[tid];
        warp_passes_u(key, k, 16, tid);
        su[tid] = key;
        __syncthreads();
    }

    int idj = (int)(key & 1023u);
    float rv = sdst_buf[(size_t)bh * N_ + idj];       // exact value
    vs[tid] = rv;
    sid_buf[(size_t)bh * N_ + tid] = idj;
    float x1 = __expf(rv);
    float x2 = __expf(0.2f * rv);
    e1s[tid] = x1; e2s[tid] = x2;
    e1_buf[(size_t)bh * N_ + tid] = x1;
    e2_buf[(size_t)bh * N_ + tid] = x2;

    // scalar scans (c1: suffix of e1; c2: prefix of e2)
    float s2 = x2;
#pragma unroll
    for (int o = 1; o < 32; o <<= 1) {
        float y = __shfl_up_sync(0xffffffffu, s2, o);
        if (lane >= o) s2 += y;
    }
    if (lane == 31) wt2[w] = s2;
    float s1 = x1;
#pragma unroll
    for (int o = 1; o < 32; o <<= 1) {
        float y = __shfl_down_sync(0xffffffffu, s1, o);
        if (lane + o < 32) s1 += y;
    }
    if (lane == 0) wt[w] = s1;
    __syncthreads();
    if (w == 0) {
        float t = wt[lane];
        float ts = t;
#pragma unroll
        for (int o = 1; o < 32; o <<= 1) {
            float y = __shfl_down_sync(0xffffffffu, ts, o);
            if (lane + o < 32) ts += y;
        }
        wo[lane] = ts - t;
        float t2 = wt2[lane];
        float ps = t2;
#pragma unroll
        for (int o = 1; o < 32; o <<= 1) {
            float y = __shfl_up_sync(0xffffffffu, ps, o);
            if (lane >= o) ps += y;
        }
        wo2[lane] = ps - t2;
    }
    __syncthreads();
    sc1[tid] = s1 + wo[w];
    sc2[tid + 1] = s2 + wo2[w];
    if (tid == 0) {
        sc1[1024] = 0.f;
        sc2[0] = 0.f;
    }
    __syncthreads();

    // ---- fused per-query scalars (binary search in smem) ----
    {
        float src = ssrc_buf[(size_t)bh * N_ + tid];
        float th = -src;
        int lo = 0, hi = 1024;
#pragma unroll
        for (int s = 0; s < 10; s++) {
            int mid = (lo + hi) >> 1;
            if (vs[mid] < th) lo = mid + 1; else hi = mid;
        }
        int t = lo;
        float vmax = vs[1023];
        float etop = src + vmax;
        float mM = (etop >= 0.f) ? etop : 0.2f * etop;
        float E1 = (t < 1024) ? __expf(src - mM) : 0.f;
        float E2 = (t > 0) ? __expf(0.2f * src - mM) : 0.f;
        float rden = 1.f / (E1 * sc1[t] + E2 * sc2[t]);
        qscal_buf[(size_t)bh * N_ + tid] =
            make_float4(E1 * rden, E2 * rden, __int_as_float(t), 0.f);
    }

    // vector chunk totals (warp w owns k in [w*32,w*32+32), lane = d)
    const float* gb = g_buf + (size_t)b * N_ * OCOLS + h * ND;
    float t1 = 0.f, t2v = 0.f;
    for (int kk = 0; kk < 32; kk++) {
        int k = (w << 5) + kk;
        int j = (int)(su[k] & 1023u);
        float gv = gb[(size_t)j * OCOLS + lane];
        t1 += e1s[k] * gv;
        t2v += e2s[k] * gv;
    }
    tot1[w][lane] = t1;
    tot2[w][lane] = t2v;
    __syncthreads();
    {
        float a1 = tot1[lane][w];   // chunk = lane, d = w
        float a2 = tot2[lane][w];
        float inc1 = a1;
#pragma unroll
        for (int o = 1; o < 32; o <<= 1) {
            float y = __shfl_down_sync(0xffffffffu, inc1, o);
            if (lane + o < 32) inc1 += y;
        }
        float inc2 = a2;
#pragma unroll
        for (int o = 1; o < 32; o <<= 1) {
            float y = __shfl_up_sync(0xffffffffu, inc2, o);
            if (lane >= o) inc2 += y;
        }
        cb1_buf[((size_t)bh * 32 + lane) * 32 + w] = inc1;        // inclusive suffix
        cb2_buf[((size_t)bh * 32 + lane) * 32 + w] = inc2 - a2;   // exclusive prefix
    }
}

// ---------------- kernel 3: merged prefix/suffix writes (full prefetch) ----------------
// grid (4, 64), 256 threads; warp wi handles chunk c = bx*8+wi, lane = d.
__global__ __launch_bounds__(256, 2) void write_k() {
    int bh = blockIdx.y;
    int b = bh >> 3, h = bh & 7;
    int wi = threadIdx.x >> 5, lane = threadIdx.x & 31;
    int c = blockIdx.x * 8 + wi;
    int k0 = c << 5;

    float is1 = cb1_buf[((size_t)bh * 32 + c) * 32 + lane];
    float r2  = cb2_buf[((size_t)bh * 32 + c) * 32 + lane];
    const float* gb = g_buf + (size_t)b * N_ * OCOLS + h * ND;
    const int* sidp = sid_buf + (size_t)bh * N_ + k0;
    const float* e1p = e1_buf + (size_t)bh * N_ + k0;
    const float* e2p = e2_buf + (size_t)bh * N_ + k0;
    float* S1 = suf1_buf + (size_t)bh * ROWS * ND;
    float* P2 = pre2_buf + (size_t)bh * ROWS * ND;

    if (c == 0) P2[lane] = 0.f;

    // prefetch all 32 gathers (MLP 32)
    float gv[32];
#pragma unroll
    for (int kk = 0; kk < 32; kk++)
        gv[kk] = gb[(size_t)sidp[kk] * OCOLS + lane];

    float p1 = 0.f;
#pragma unroll
    for (int kk = 0; kk < 32; kk++) {
        int k = k0 + kk;
        S1[(size_t)k * ND + lane] = is1 - p1;
        p1 = fmaf(e1p[kk], gv[kk], p1);
        r2 = fmaf(e2p[kk], gv[kk], r2);
        P2[(size_t)(k + 1) * ND + lane] = r2;
    }
    if (c == 31) S1[(size_t)1024 * ND + lane] = 0.f;
}

// ---------------- kernel 4: output (float4/thread) ----------------
__global__ __launch_bounds__(256) void out_k(float* __restrict__ out) {
    int idx = blockIdx.x * 256 + threadIdx.x;
    int e = idx << 2;
    int m = e >> 8, cc = e & 255;
    int h = cc >> 5, d0 = cc & 31;
    int b = m >> 10, i = m & 1023;
    int bh = b * NH + h;
    float4 s = qscal_buf[(size_t)bh * N_ + i];
    int t = __float_as_int(s.z);
    size_t base = ((size_t)bh * ROWS + t) * ND + d0;
    float4 sf = *(const float4*)(suf1_buf + base);
    float4 pf = *(const float4*)(pre2_buf + base);
    float4 o;
    o.x = s.x * sf.x + s.y * pf.x;
    o.y = s.x * sf.y + s.y * pf.y;
    o.z = s.x * sf.z + s.y * pf.z;
    o.w = s.x * sf.w + s.y * pf.w;
    *(float4*)(out + e) = o;
}

// ---------------- launcher ----------------
extern "C" void kernel_launch(void* const* d_in, const int* in_sizes, int n_in,
                              void* d_out, int out_size) {
    const float* vertex = (const float*)d_in[0];
    const float* w_vert = (const float*)d_in[1];
    const float* attn_w = (const float*)d_in[2];
    float* out = (float*)d_out;

    dim3 gG(2, 128);
    gemm_mma_k<<<gG, 256>>>(vertex, w_vert, attn_w);
    prep_k<<<NBH, 1024>>>();
    write_k<<<dim3(4, NBH), 256>>>();
    out_k<<<M_TOT * OCOLS / 4 / 256, 256>>>(out);
}